// round 16
// baseline (speedup 1.0000x reference)
#include <cuda_runtime.h>
#include <cuda_bf16.h>
#include <cstdint>

// Problem constants
#define B    256
#define T    256
#define NQ   1000
#define DK   128
#define DV   128
#define CC   32
#define TOUT 255
#define NROWS (B * TOUT)         // 65280

typedef unsigned long long u64;
typedef unsigned int u32;

// ---------------- packed f32x2 helpers (sm_103a) --------------------------
__device__ __forceinline__ u64 pack2(float lo, float hi) {
    u64 r; asm("mov.b64 %0, {%1, %2};" : "=l"(r) : "f"(lo), "f"(hi)); return r;
}
__device__ __forceinline__ void unpack2(u64 v, float& lo, float& hi) {
    asm("mov.b64 {%0, %1}, %2;" : "=f"(lo), "=f"(hi) : "l"(v));
}
__device__ __forceinline__ u64 fma2(u64 a, u64 b, u64 c) {
    u64 d; asm("fma.rn.f32x2 %0, %1, %2, %3;" : "=l"(d) : "l"(a), "l"(b), "l"(c)); return d;
}
// pack two fp32 -> bf16x2 register: first arg -> LOWER half (k even), second -> upper.
__device__ __forceinline__ u32 bfpack(float lo, float hi) {
    u32 r; asm("cvt.rn.bf16x2.f32 %0, %1, %2;" : "=r"(r) : "f"(hi), "f"(lo)); return r;
}

// ---------------- device scratch ------------------------------------------
__device__ __align__(16) float  g_wt[NQ * CC];        // softmax(k_emb @ Mk)
__device__ __align__(16) float  g_g [NQ * DK];        // k_emb @ f_W[128:] + f_b
__device__ __align__(16) float2 g_ea[2 * NQ * DV];    // (-sigmoid(vW_e), tanh(vW_a))
__device__ __align__(16) float  g_rt[NROWS * DV];     // rt scratch
__device__ __align__(16) u64    g_bf[16 * 16 * 32];   // f_W bf16 hi/lo mma B-fragments

// ---------------- fused precompute (round-14, byte-exact) ------------------
#define EA_BLOCKS 125
#define WT_BLOCKS 125
#define PG_BLOCKS 63
#define BF_BLOCKS 32
#define PRE_BLOCKS (EA_BLOCKS + WT_BLOCKS + PG_BLOCKS + BF_BLOCKS)

__global__ void __launch_bounds__(256)
pre_fused_kernel(const float* __restrict__ k_emb,
                 const float* __restrict__ v_emb,
                 const float* __restrict__ Mk,
                 const float* __restrict__ f_W,
                 const float* __restrict__ f_b,
                 const float* __restrict__ e_W,
                 const float* __restrict__ e_b,
                 const float* __restrict__ a_W,
                 const float* __restrict__ a_b) {
    __shared__ __align__(16) float sbuf[16 * DK];
    int bid = blockIdx.x;
    int tid = threadIdx.x;

    if (bid < EA_BLOCKS) {
        // ---- pre_ea: (-e, a) for 16 rows ----
        int row0 = bid * 16;
        int j  = tid & 127;
        int rh = tid >> 7;
        #pragma unroll
        for (int u = 0; u < 2; u++) {
            int idx = tid + u * 256;
            reinterpret_cast<float4*>(sbuf)[idx] =
                __ldg(reinterpret_cast<const float4*>(v_emb + row0 * DV) + idx);
        }
        __syncthreads();

        float acce[8], acca[8];
        float eb = __ldg(e_b + j), ab = __ldg(a_b + j);
        #pragma unroll
        for (int r = 0; r < 8; r++) { acce[r] = eb; acca[r] = ab; }

        const float* xb = sbuf + rh * 8 * DV;
        #pragma unroll 4
        for (int k = 0; k < DV; k += 4) {
            float we0 = __ldg(e_W + (k + 0) * DV + j);
            float we1 = __ldg(e_W + (k + 1) * DV + j);
            float we2 = __ldg(e_W + (k + 2) * DV + j);
            float we3 = __ldg(e_W + (k + 3) * DV + j);
            float wa0 = __ldg(a_W + (k + 0) * DV + j);
            float wa1 = __ldg(a_W + (k + 1) * DV + j);
            float wa2 = __ldg(a_W + (k + 2) * DV + j);
            float wa3 = __ldg(a_W + (k + 3) * DV + j);
            #pragma unroll
            for (int r = 0; r < 8; r++) {
                float4 xv = *reinterpret_cast<const float4*>(xb + r * DV + k);
                acce[r] = fmaf(xv.x, we0, acce[r]);
                acce[r] = fmaf(xv.y, we1, acce[r]);
                acce[r] = fmaf(xv.z, we2, acce[r]);
                acce[r] = fmaf(xv.w, we3, acce[r]);
                acca[r] = fmaf(xv.x, wa0, acca[r]);
                acca[r] = fmaf(xv.y, wa1, acca[r]);
                acca[r] = fmaf(xv.z, wa2, acca[r]);
                acca[r] = fmaf(xv.w, wa3, acca[r]);
            }
        }
        #pragma unroll
        for (int r = 0; r < 8; r++) {
            int gr = row0 + rh * 8 + r;
            g_ea[gr * DV + j] = make_float2(-1.0f / (1.0f + expf(-acce[r])),
                                            tanhf(acca[r]));
        }
    } else if (bid < EA_BLOCKS + WT_BLOCKS) {
        // ---- pre_wt: softmax(k_emb @ Mk), one q per warp ----
        int warp = tid >> 5;
        int lane = tid & 31;
        int q = (bid - EA_BLOCKS) * 8 + warp;
        const float* krow = k_emb + q * DK;
        float acc = 0.f;
        #pragma unroll 8
        for (int k = 0; k < DK; k++)
            acc = fmaf(__ldg(krow + k), __ldg(Mk + k * CC + lane), acc);
        float mx = acc;
        #pragma unroll
        for (int off = 16; off; off >>= 1)
            mx = fmaxf(mx, __shfl_xor_sync(0xffffffffu, mx, off));
        float e = expf(acc - mx);
        float s = e;
        #pragma unroll
        for (int off = 16; off; off >>= 1)
            s += __shfl_xor_sync(0xffffffffu, s, off);
        g_wt[q * CC + lane] = e / s;
    } else if (bid < EA_BLOCKS + WT_BLOCKS + PG_BLOCKS) {
        // ---- pre_g: g = k_emb @ f_W[128:] + f_b, 16 rows ----
        int row0 = (bid - EA_BLOCKS - WT_BLOCKS) * 16;
        int j  = tid & 127;
        int rh = tid >> 7;
        #pragma unroll
        for (int u = 0; u < 2; u++) {
            int idx = tid + u * 256;
            int r   = idx >> 5;
            int gr  = row0 + r; if (gr >= NQ) gr = NQ - 1;
            reinterpret_cast<float4*>(sbuf)[idx] =
                __ldg(reinterpret_cast<const float4*>(k_emb + gr * DK) + (idx & 31));
        }
        __syncthreads();

        float acc[8];
        float fb = __ldg(f_b + j);
        #pragma unroll
        for (int r = 0; r < 8; r++) acc[r] = fb;

        const float* xb = sbuf + rh * 8 * DK;
        #pragma unroll 4
        for (int k = 0; k < DK; k += 4) {
            float w0 = __ldg(f_W + (DK + k + 0) * DK + j);
            float w1 = __ldg(f_W + (DK + k + 1) * DK + j);
            float w2 = __ldg(f_W + (DK + k + 2) * DK + j);
            float w3 = __ldg(f_W + (DK + k + 3) * DK + j);
            #pragma unroll
            for (int r = 0; r < 8; r++) {
                float4 xv = *reinterpret_cast<const float4*>(xb + r * DK + k);
                acc[r] = fmaf(xv.x, w0, acc[r]);
                acc[r] = fmaf(xv.y, w1, acc[r]);
                acc[r] = fmaf(xv.z, w2, acc[r]);
                acc[r] = fmaf(xv.w, w3, acc[r]);
            }
        }
        #pragma unroll
        for (int r = 0; r < 8; r++) {
            int gr = row0 + rh * 8 + r;
            if (gr < NQ) g_g[gr * DK + j] = acc[r];
        }
    } else {
        // ---- BF role: build f_W bf16 hi/lo B-fragments in m16n8k16 layout --
        int idx = (bid - EA_BLOCKS - WT_BLOCKS - PG_BLOCKS) * 256 + tid; // 0..8191
        int kt4  = idx >> 9;
        int ntg  = (idx >> 5) & 15;
        int lane = idx & 31;
        int tg = lane & 3, gid = lane >> 2;
        int n  = ntg * 8 + gid;
        int kb = (kt4 & 7) * 16 + tg * 2;
        bool ishi = (kt4 < 8);
        u32 v[4];
        #pragma unroll
        for (int r = 0; r < 4; r++) {
            int k = kb + (r & 1) + ((r >> 1) * 8);   // k0,k0+1,k0+8,k0+9
            float w = __ldg(f_W + k * DK + n);
            __nv_bfloat16 h = __float2bfloat16(w);
            float hf = __bfloat162float(h);
            __nv_bfloat16 outv = ishi ? h : __float2bfloat16(w - hf);
            v[r] = (u32)*reinterpret_cast<unsigned short*>(&outv);
        }
        u32 b0 = v[0] | (v[1] << 16);
        u32 b1 = v[2] | (v[3] << 16);
        g_bf[idx] = (u64)b0 | ((u64)b1 << 32);
    }
}

// ---------------- sequential scan (round-9 core; .cg via INTRINSICS) -------
// E gathers use __ldcg (L1-bypass, schedulable), rt stores use __stcg.
// No asm volatile in the load/store path -> compiler keeps the pipeline.

__device__ __forceinline__ void scan_loadW(int s, u64 W2[16]) {
    const ulonglong2* wp = reinterpret_cast<const ulonglong2*>(g_wt + s * CC);
    #pragma unroll
    for (int u = 0; u < 8; u++) {
        ulonglong2 v = __ldg(wp + u);
        W2[2 * u]     = v.x;
        W2[2 * u + 1] = v.y;
    }
}

__device__ __forceinline__ float scan_step(u64 m2[16], const u64 W2[16],
                                           float ne, float a) {
    u64 en2 = pack2(ne, ne);
    u64 a2  = pack2(a, a);
    u64 acc0 = 0ull, acc1 = 0ull;
    #pragma unroll
    for (int p = 0; p < 16; p++) {
        u64 mo = m2[p];
        if (p & 1) acc1 = fma2(W2[p], mo, acc1);
        else       acc0 = fma2(W2[p], mo, acc0);
        u64 tmp = fma2(mo, en2, a2);          // a - e*m
        m2[p] = fma2(W2[p], tmp, mo);         // m + w*(a - e*m)
    }
    float x0, x1, y0, y1;
    unpack2(acc0, x0, x1);
    unpack2(acc1, y0, y1);
    return (x0 + x1) + (y0 + y1);
}

__global__ void __launch_bounds__(128, 1)
scan_kernel(const int* __restrict__ skills,
            const int* __restrict__ responses,
            const float* __restrict__ Mv0) {
    int tid  = threadIdx.x;
    int half = tid >> 6;                 // 0/1 -> batch within block
    int td   = tid & 63;
    int b    = blockIdx.x * 2 + half;
    int d0   = td;
    int d1   = td + 64;

    u64 m0[16], m1[16];
    #pragma unroll
    for (int p = 0; p < 16; p++) {
        m0[p] = pack2(__ldg(Mv0 + (2 * p) * DV + d0),
                      __ldg(Mv0 + (2 * p + 1) * DV + d0));
        m1[p] = pack2(__ldg(Mv0 + (2 * p) * DV + d1),
                      __ldg(Mv0 + (2 * p + 1) * DV + d1));
    }

    const int* srow = skills + b * T;
    const int* rrow = responses + b * T;
    float* rtp0 = g_rt + (b * TOUT) * DV + d0;
    float* rtp1 = g_rt + (b * TOUT) * DV + d1;

    int    sE[8];
    float2 E0[8], E1[8];
    #pragma unroll
    for (int k = 0; k < 8; k++) {
        int s = __ldg(srow + k);
        int q = s + NQ * __ldg(rrow + k);
        sE[k] = s;
        E0[k] = __ldcg(g_ea + q * DV + d0);
        E1[k] = __ldcg(g_ea + q * DV + d1);
    }
    int sCur = __ldg(srow + 8);
    int qCur = sCur + NQ * __ldg(rrow + 8);

    u64 WA[16], WB[16];
    scan_loadW(sE[0], WA);

#define SCAN_BODY_STEP(k, Wc, Wn)                                          \
    {                                                                      \
        scan_loadW(sE[((k) + 1) & 7], Wn);                                 \
        __stcg(rtp0 + (t + (k)) * DV, scan_step(m0, Wc, E0[k].x, E0[k].y)); \
        __stcg(rtp1 + (t + (k)) * DV, scan_step(m1, Wc, E1[k].x, E1[k].y)); \
        E0[k] = __ldcg(g_ea + qCur * DV + d0);                             \
        E1[k] = __ldcg(g_ea + qCur * DV + d1);                             \
        sE[k] = sCur;                                                      \
        int ni = t + 9 + (k); if (ni > T - 1) ni = T - 1;                  \
        sCur = __ldg(srow + ni);                                           \
        qCur = sCur + NQ * __ldg(rrow + ni);                               \
    }

    for (int t = 0; t < 248; t += 8) {
        SCAN_BODY_STEP(0, WA, WB)
        SCAN_BODY_STEP(1, WB, WA)
        SCAN_BODY_STEP(2, WA, WB)
        SCAN_BODY_STEP(3, WB, WA)
        SCAN_BODY_STEP(4, WA, WB)
        SCAN_BODY_STEP(5, WB, WA)
        SCAN_BODY_STEP(6, WA, WB)
        SCAN_BODY_STEP(7, WB, WA)
    }
#undef SCAN_BODY_STEP

    {
        const int t = 248;
#define SCAN_TAIL_STEP(k, Wc, Wn)                                          \
        {                                                                  \
            scan_loadW(sE[(k) + 1], Wn);                                   \
            __stcg(rtp0 + (t + (k)) * DV, scan_step(m0, Wc, E0[k].x, E0[k].y)); \
            __stcg(rtp1 + (t + (k)) * DV, scan_step(m1, Wc, E1[k].x, E1[k].y)); \
        }
        SCAN_TAIL_STEP(0, WA, WB)
        SCAN_TAIL_STEP(1, WB, WA)
        SCAN_TAIL_STEP(2, WA, WB)
        SCAN_TAIL_STEP(3, WB, WA)
        SCAN_TAIL_STEP(4, WA, WB)
        SCAN_TAIL_STEP(5, WB, WA)
        __stcg(rtp0 + 254 * DV, scan_step(m0, WA, E0[6].x, E0[6].y));
        __stcg(rtp1 + 254 * DV, scan_step(m1, WA, E1[6].x, E1[6].y));
#undef SCAN_TAIL_STEP
    }
}

// ---------------- readout via mma.sync (round-14, byte-exact) --------------
#define XPAD 132

__device__ __forceinline__ void mma16816(float c[4], const u32 a[4],
                                         u32 b0, u32 b1) {
    asm volatile(
        "mma.sync.aligned.m16n8k16.row.col.f32.bf16.bf16.f32 "
        "{%0,%1,%2,%3}, {%4,%5,%6,%7}, {%8,%9}, {%0,%1,%2,%3};"
        : "+f"(c[0]), "+f"(c[1]), "+f"(c[2]), "+f"(c[3])
        : "r"(a[0]), "r"(a[1]), "r"(a[2]), "r"(a[3]), "r"(b0), "r"(b1));
}

__global__ void __launch_bounds__(256)
readout_kernel(const float* __restrict__ p_W,
               const float* __restrict__ p_b,
               const int* __restrict__ skills,
               const int* __restrict__ responses,
               float* __restrict__ out,
               float* __restrict__ out2) {
    __shared__ __align__(16) float xs[64 * XPAD];
    __shared__ float red[64][2];

    int tid  = threadIdx.x;
    int lane = tid & 31;
    int wid  = tid >> 5;
    int wm   = wid & 3;
    int wn   = wid >> 2;
    int tg   = lane & 3;
    int gid  = lane >> 2;
    int row0 = blockIdx.x * 64;

    // stage X tile (64 x 128 fp32) with pad
    {
        const float4* src = reinterpret_cast<const float4*>(g_rt + row0 * DK);
        #pragma unroll
        for (int u = 0; u < 8; u++) {
            int fidx = tid + u * 256;          // 2048 float4
            int r = fidx >> 5, c4 = fidx & 31;
            *reinterpret_cast<float4*>(xs + r * XPAD + c4 * 4) = __ldg(src + fidx);
        }
    }
    __syncthreads();

    const float* xlo_row = xs + (wm * 16 + gid) * XPAD;
    const float* xhi_row = xlo_row + 8 * XPAD;

    float acc[8][4];
    #pragma unroll
    for (int nt = 0; nt < 8; nt++)
        #pragma unroll
        for (int e = 0; e < 4; e++) acc[nt][e] = 0.f;

    u32 AH[8][4];
    const u64* bbase = g_bf + (wn * 8) * 32 + lane;

    #pragma unroll
    for (int kt = 0; kt < 24; kt++) {
        u32 a[4];
        int kc = (kt & 7) * 16 + tg * 2;
        if (kt < 8) {
            float2 x0 = *reinterpret_cast<const float2*>(xlo_row + kc);
            float2 x1 = *reinterpret_cast<const float2*>(xhi_row + kc);
            float2 x2 = *reinterpret_cast<const float2*>(xlo_row + kc + 8);
            float2 x3 = *reinterpret_cast<const float2*>(xhi_row + kc + 8);
            a[0] = bfpack(x0.x, x0.y);
            a[1] = bfpack(x1.x, x1.y);
            a[2] = bfpack(x2.x, x2.y);
            a[3] = bfpack(x3.x, x3.y);
            #pragma unroll
            for (int r = 0; r < 4; r++) AH[kt][r] = a[r];
        } else if (kt < 16) {
            float2 xv[4];
            xv[0] = *reinterpret_cast<const float2*>(xlo_row + kc);
            xv[1] = *reinterpret_cast<const float2*>(xhi_row + kc);
            xv[2] = *reinterpret_cast<const float2*>(xlo_row + kc + 8);
            xv[3] = *reinterpret_cast<const float2*>(xhi_row + kc + 8);
            #pragma unroll
            for (int r = 0; r < 4; r++) {
                u32 h = AH[kt - 8][r];
                float h0 = __uint_as_float(h << 16);
                float h1 = __uint_as_float(h & 0xFFFF0000u);
                a[r] = bfpack(xv[r].x - h0, xv[r].y - h1);
            }
        } else {
            #pragma unroll
            for (int r = 0; r < 4; r++) a[r] = AH[kt - 16][r];
        }
        int bkt = (kt >= 16) ? (8 + (kt & 7)) : (kt & 7);
        const u64* bp = bbase + (bkt << 9);
        #pragma unroll
        for (int nt = 0; nt < 8; nt++) {
            u64 bv = __ldg(bp + nt * 32);
            mma16816(acc[nt], a, (u32)bv, (u32)(bv >> 32));
        }
    }

    // epilogue: + g gather, tanh, dot p_W, reduce
    int r_lo = row0 + wm * 16 + gid;
    int r_hi = r_lo + 8;
    int bb_lo = r_lo / TOUT, tt_lo = r_lo - bb_lo * TOUT;
    int bb_hi = r_hi / TOUT, tt_hi = r_hi - bb_hi * TOUT;
    int sk_lo = __ldg(skills + bb_lo * T + tt_lo);
    int sk_hi = __ldg(skills + bb_hi * T + tt_hi);

    float s_lo = 0.f, s_hi = 0.f;
    #pragma unroll
    for (int nt = 0; nt < 8; nt++) {
        int jg = wn * 64 + nt * 8 + tg * 2;
        float2 pw  = __ldg(reinterpret_cast<const float2*>(p_W + jg));
        float2 glo = __ldg(reinterpret_cast<const float2*>(g_g + sk_lo * DK + jg));
        float2 ghi = __ldg(reinterpret_cast<const float2*>(g_g + sk_hi * DK + jg));
        s_lo = fmaf(tanhf(acc[nt][0] + glo.x), pw.x, s_lo);
        s_lo = fmaf(tanhf(acc[nt][1] + glo.y), pw.y, s_lo);
        s_hi = fmaf(tanhf(acc[nt][2] + ghi.x), pw.x, s_hi);
        s_hi = fmaf(tanhf(acc[nt][3] + ghi.y), pw.y, s_hi);
    }
    s_lo += __shfl_xor_sync(0xffffffffu, s_lo, 1);
    s_lo += __shfl_xor_sync(0xffffffffu, s_lo, 2);
    s_hi += __shfl_xor_sync(0xffffffffu, s_hi, 1);
    s_hi += __shfl_xor_sync(0xffffffffu, s_hi, 2);
    if (tg == 0) {
        red[wm * 16 + gid][wn]     = s_lo;
        red[wm * 16 + gid + 8][wn] = s_hi;
    }
    __syncthreads();

    if (tid < 64) {
        float s = red[tid][0] + red[tid][1] + __ldg(p_b);
        int gr = row0 + tid;
        int bb = gr / TOUT;
        int tt = gr - bb * TOUT;
        out[gr]  = 1.0f / (1.0f + expf(-s));
        out2[gr] = (float)__ldg(responses + bb * T + tt + 1);
    }
}

// ---------------- launch ----------------------------------------------------
extern "C" void kernel_launch(void* const* d_in, const int* in_sizes, int n_in,
                              void* d_out, int out_size) {
    const int*   skills    = (const int*)  d_in[0];
    const int*   responses = (const int*)  d_in[1];
    const float* k_emb     = (const float*)d_in[2];
    const float* v_emb     = (const float*)d_in[3];
    const float* Mk        = (const float*)d_in[4];
    const float* Mv0       = (const float*)d_in[5];
    const float* f_W       = (const float*)d_in[6];
    const float* f_b       = (const float*)d_in[7];
    const float* p_W       = (const float*)d_in[8];
    const float* p_b       = (const float*)d_in[9];
    const float* e_W       = (const float*)d_in[10];
    const float* e_b       = (const float*)d_in[11];
    const float* a_W       = (const float*)d_in[12];
    const float* a_b       = (const float*)d_in[13];

    float* pred_out = (float*)d_out;
    float* true_out = pred_out + (out_size / 2);

    pre_fused_kernel<<<PRE_BLOCKS, 256>>>(k_emb, v_emb, Mk, f_W, f_b,
                                          e_W, e_b, a_W, a_b);

    scan_kernel<<<B / 2, 128>>>(skills, responses, Mv0);

    readout_kernel<<<NROWS / 64, 256>>>(p_W, p_b, skills, responses,
                                        pred_out, true_out);
}

// round 17
// speedup vs baseline: 1.0945x; 1.0945x over previous
#include <cuda_runtime.h>
#include <cuda_bf16.h>
#include <cstdint>

// Problem constants
#define B    256
#define T    256
#define NQ   1000
#define DK   128
#define DV   128
#define CC   32
#define TOUT 255
#define NROWS (B * TOUT)         // 65280

typedef unsigned long long u64;
typedef unsigned int u32;

// ---------------- packed f32x2 helpers (sm_103a) --------------------------
__device__ __forceinline__ u64 pack2(float lo, float hi) {
    u64 r; asm("mov.b64 %0, {%1, %2};" : "=l"(r) : "f"(lo), "f"(hi)); return r;
}
__device__ __forceinline__ void unpack2(u64 v, float& lo, float& hi) {
    asm("mov.b64 {%0, %1}, %2;" : "=f"(lo), "=f"(hi) : "l"(v));
}
__device__ __forceinline__ u64 fma2(u64 a, u64 b, u64 c) {
    u64 d; asm("fma.rn.f32x2 %0, %1, %2, %3;" : "=l"(d) : "l"(a), "l"(b), "l"(c)); return d;
}
// pack two fp32 -> bf16x2 register: first arg -> LOWER half (k even), second -> upper.
__device__ __forceinline__ u32 bfpack(float lo, float hi) {
    u32 r; asm("cvt.rn.bf16x2.f32 %0, %1, %2;" : "=r"(r) : "f"(hi), "f"(lo)); return r;
}

// ---------------- device scratch ------------------------------------------
__device__ __align__(16) float  g_wt[NQ * CC];        // softmax(k_emb @ Mk)
__device__ __align__(16) float  g_g [NQ * DK];        // k_emb @ f_W[128:] + f_b
__device__ __align__(16) float2 g_ea[2 * NQ * DV];    // (-sigmoid(vW_e), tanh(vW_a))
__device__ __align__(16) float  g_rt[NROWS * DV];     // rt scratch
__device__ __align__(16) u64    g_bf[16 * 16 * 32];   // f_W bf16 hi/lo mma B-fragments
__device__ __align__(16) u64    g_be[16 * 16 * 32];   // e_W fragments
__device__ __align__(16) u64    g_ba[16 * 16 * 32];   // a_W fragments

// ---------------- mma helper ------------------------------------------------
__device__ __forceinline__ void mma16816(float c[4], const u32 a[4],
                                         u32 b0, u32 b1) {
    asm volatile(
        "mma.sync.aligned.m16n8k16.row.col.f32.bf16.bf16.f32 "
        "{%0,%1,%2,%3}, {%4,%5,%6,%7}, {%8,%9}, {%0,%1,%2,%3};"
        : "+f"(c[0]), "+f"(c[1]), "+f"(c[2]), "+f"(c[3])
        : "r"(a[0]), "r"(a[1]), "r"(a[2]), "r"(a[3]), "r"(b0), "r"(b1));
}

// ---------------- pre stage 1: WT + PG + 3x fragment packing ---------------
#define WT_BLOCKS 125
#define PG_BLOCKS 63
#define BF_BLOCKS 32
#define P1_BLOCKS (WT_BLOCKS + PG_BLOCKS + 3 * BF_BLOCKS)

__device__ __forceinline__ void pack_frag_role(const float* __restrict__ W,
                                               u64* __restrict__ dst, int idx) {
    int kt4  = idx >> 9;
    int ntg  = (idx >> 5) & 15;
    int lane = idx & 31;
    int tg = lane & 3, gid = lane >> 2;
    int n  = ntg * 8 + gid;
    int kb = (kt4 & 7) * 16 + tg * 2;
    bool ishi = (kt4 < 8);
    u32 v[4];
    #pragma unroll
    for (int r = 0; r < 4; r++) {
        int k = kb + (r & 1) + ((r >> 1) * 8);   // k0,k0+1,k0+8,k0+9
        float w = __ldg(W + k * DK + n);
        __nv_bfloat16 h = __float2bfloat16(w);
        float hf = __bfloat162float(h);
        __nv_bfloat16 outv = ishi ? h : __float2bfloat16(w - hf);
        v[r] = (u32)*reinterpret_cast<unsigned short*>(&outv);
    }
    u32 b0 = v[0] | (v[1] << 16);
    u32 b1 = v[2] | (v[3] << 16);
    dst[idx] = (u64)b0 | ((u64)b1 << 32);
}

__global__ void __launch_bounds__(256)
pre_pack_kernel(const float* __restrict__ k_emb,
                const float* __restrict__ Mk,
                const float* __restrict__ f_W,
                const float* __restrict__ f_b,
                const float* __restrict__ e_W,
                const float* __restrict__ a_W) {
    __shared__ __align__(16) float sbuf[16 * DK];
    int bid = blockIdx.x;
    int tid = threadIdx.x;

    if (bid < WT_BLOCKS) {
        // ---- pre_wt: softmax(k_emb @ Mk), one q per warp ----
        int warp = tid >> 5;
        int lane = tid & 31;
        int q = bid * 8 + warp;                  // < 1000 exactly
        const float* krow = k_emb + q * DK;
        float acc = 0.f;
        #pragma unroll 8
        for (int k = 0; k < DK; k++)
            acc = fmaf(__ldg(krow + k), __ldg(Mk + k * CC + lane), acc);
        float mx = acc;
        #pragma unroll
        for (int off = 16; off; off >>= 1)
            mx = fmaxf(mx, __shfl_xor_sync(0xffffffffu, mx, off));
        float e = expf(acc - mx);
        float s = e;
        #pragma unroll
        for (int off = 16; off; off >>= 1)
            s += __shfl_xor_sync(0xffffffffu, s, off);
        g_wt[q * CC + lane] = e / s;
    } else if (bid < WT_BLOCKS + PG_BLOCKS) {
        // ---- pre_g: g = k_emb @ f_W[128:] + f_b, 16 rows ----
        int row0 = (bid - WT_BLOCKS) * 16;
        int j  = tid & 127;
        int rh = tid >> 7;
        #pragma unroll
        for (int u = 0; u < 2; u++) {
            int idx = tid + u * 256;
            int r   = idx >> 5;
            int gr  = row0 + r; if (gr >= NQ) gr = NQ - 1;
            reinterpret_cast<float4*>(sbuf)[idx] =
                __ldg(reinterpret_cast<const float4*>(k_emb + gr * DK) + (idx & 31));
        }
        __syncthreads();

        float acc[8];
        float fb = __ldg(f_b + j);
        #pragma unroll
        for (int r = 0; r < 8; r++) acc[r] = fb;

        const float* xb = sbuf + rh * 8 * DK;
        #pragma unroll 4
        for (int k = 0; k < DK; k += 4) {
            float w0 = __ldg(f_W + (DK + k + 0) * DK + j);
            float w1 = __ldg(f_W + (DK + k + 1) * DK + j);
            float w2 = __ldg(f_W + (DK + k + 2) * DK + j);
            float w3 = __ldg(f_W + (DK + k + 3) * DK + j);
            #pragma unroll
            for (int r = 0; r < 8; r++) {
                float4 xv = *reinterpret_cast<const float4*>(xb + r * DK + k);
                acc[r] = fmaf(xv.x, w0, acc[r]);
                acc[r] = fmaf(xv.y, w1, acc[r]);
                acc[r] = fmaf(xv.z, w2, acc[r]);
                acc[r] = fmaf(xv.w, w3, acc[r]);
            }
        }
        #pragma unroll
        for (int r = 0; r < 8; r++) {
            int gr = row0 + rh * 8 + r;
            if (gr < NQ) g_g[gr * DK + j] = acc[r];
        }
    } else if (bid < WT_BLOCKS + PG_BLOCKS + BF_BLOCKS) {
        pack_frag_role(f_W, g_bf, (bid - WT_BLOCKS - PG_BLOCKS) * 256 + tid);
    } else if (bid < WT_BLOCKS + PG_BLOCKS + 2 * BF_BLOCKS) {
        pack_frag_role(e_W, g_be, (bid - WT_BLOCKS - PG_BLOCKS - BF_BLOCKS) * 256 + tid);
    } else {
        pack_frag_role(a_W, g_ba, (bid - WT_BLOCKS - PG_BLOCKS - 2 * BF_BLOCKS) * 256 + tid);
    }
}

// ---------------- pre stage 2: EA via mma.sync ------------------------------
// 64 v_emb rows x 128 cols per block; both e_W and a_W GEMMs share A frags.
#define XPAD 132
#define EA2_BLOCKS ((2 * NQ + 63) / 64)   // 32

__global__ void __launch_bounds__(256)
pre_ea_mma_kernel(const float* __restrict__ v_emb,
                  const float* __restrict__ e_b,
                  const float* __restrict__ a_b) {
    __shared__ __align__(16) float xs[64 * XPAD];

    int tid  = threadIdx.x;
    int lane = tid & 31;
    int wid  = tid >> 5;
    int wm   = wid & 3;
    int wn   = wid >> 2;
    int tg   = lane & 3;
    int gid  = lane >> 2;
    int row0 = blockIdx.x * 64;

    // stage v_emb tile (clamped)
    {
        #pragma unroll
        for (int u = 0; u < 8; u++) {
            int fidx = tid + u * 256;          // 2048 float4
            int r = fidx >> 5, c4 = fidx & 31;
            int gr = row0 + r; if (gr >= 2 * NQ) gr = 2 * NQ - 1;
            *reinterpret_cast<float4*>(xs + r * XPAD + c4 * 4) =
                __ldg(reinterpret_cast<const float4*>(v_emb + gr * DV) + c4);
        }
    }
    __syncthreads();

    const float* xlo_row = xs + (wm * 16 + gid) * XPAD;
    const float* xhi_row = xlo_row + 8 * XPAD;

    float acce[8][4], acca[8][4];
    #pragma unroll
    for (int nt = 0; nt < 8; nt++)
        #pragma unroll
        for (int e = 0; e < 4; e++) { acce[nt][e] = 0.f; acca[nt][e] = 0.f; }

    u32 AH[8][4];
    const u64* bbase_e = g_be + (wn * 8) * 32 + lane;
    const u64* bbase_a = g_ba + (wn * 8) * 32 + lane;

    #pragma unroll
    for (int kt = 0; kt < 24; kt++) {
        u32 a[4];
        int kc = (kt & 7) * 16 + tg * 2;
        if (kt < 8) {
            float2 x0 = *reinterpret_cast<const float2*>(xlo_row + kc);
            float2 x1 = *reinterpret_cast<const float2*>(xhi_row + kc);
            float2 x2 = *reinterpret_cast<const float2*>(xlo_row + kc + 8);
            float2 x3 = *reinterpret_cast<const float2*>(xhi_row + kc + 8);
            a[0] = bfpack(x0.x, x0.y);
            a[1] = bfpack(x1.x, x1.y);
            a[2] = bfpack(x2.x, x2.y);
            a[3] = bfpack(x3.x, x3.y);
            #pragma unroll
            for (int r = 0; r < 4; r++) AH[kt][r] = a[r];
        } else if (kt < 16) {
            float2 xv[4];
            xv[0] = *reinterpret_cast<const float2*>(xlo_row + kc);
            xv[1] = *reinterpret_cast<const float2*>(xhi_row + kc);
            xv[2] = *reinterpret_cast<const float2*>(xlo_row + kc + 8);
            xv[3] = *reinterpret_cast<const float2*>(xhi_row + kc + 8);
            #pragma unroll
            for (int r = 0; r < 4; r++) {
                u32 h = AH[kt - 8][r];
                float h0 = __uint_as_float(h << 16);
                float h1 = __uint_as_float(h & 0xFFFF0000u);
                a[r] = bfpack(xv[r].x - h0, xv[r].y - h1);
            }
        } else {
            #pragma unroll
            for (int r = 0; r < 4; r++) a[r] = AH[kt - 16][r];
        }
        int bkt = (kt >= 16) ? (8 + (kt & 7)) : (kt & 7);
        const u64* bpe = bbase_e + (bkt << 9);
        const u64* bpa = bbase_a + (bkt << 9);
        #pragma unroll
        for (int nt = 0; nt < 8; nt++) {
            u64 bve = __ldg(bpe + nt * 32);
            mma16816(acce[nt], a, (u32)bve, (u32)(bve >> 32));
            u64 bva = __ldg(bpa + nt * 32);
            mma16816(acca[nt], a, (u32)bva, (u32)(bva >> 32));
        }
    }

    // epilogue: bias + activations -> g_ea
    int r_lo = row0 + wm * 16 + gid;
    int r_hi = r_lo + 8;
    #pragma unroll
    for (int nt = 0; nt < 8; nt++) {
        int jg = wn * 64 + nt * 8 + tg * 2;
        float2 ebv = __ldg(reinterpret_cast<const float2*>(e_b + jg));
        float2 abv = __ldg(reinterpret_cast<const float2*>(a_b + jg));
        if (r_lo < 2 * NQ) {
            g_ea[r_lo * DV + jg] =
                make_float2(-1.0f / (1.0f + expf(-(acce[nt][0] + ebv.x))),
                            tanhf(acca[nt][0] + abv.x));
            g_ea[r_lo * DV + jg + 1] =
                make_float2(-1.0f / (1.0f + expf(-(acce[nt][1] + ebv.y))),
                            tanhf(acca[nt][1] + abv.y));
        }
        if (r_hi < 2 * NQ) {
            g_ea[r_hi * DV + jg] =
                make_float2(-1.0f / (1.0f + expf(-(acce[nt][2] + ebv.x))),
                            tanhf(acca[nt][2] + abv.x));
            g_ea[r_hi * DV + jg + 1] =
                make_float2(-1.0f / (1.0f + expf(-(acce[nt][3] + ebv.y))),
                            tanhf(acca[nt][3] + abv.y));
        }
    }
}

// ---------------- sequential scan (round-14/round-9, byte-exact) -----------
__device__ __forceinline__ void scan_loadW(int s, u64 W2[16]) {
    const ulonglong2* wp = reinterpret_cast<const ulonglong2*>(g_wt + s * CC);
    #pragma unroll
    for (int u = 0; u < 8; u++) {
        ulonglong2 v = __ldg(wp + u);
        W2[2 * u]     = v.x;
        W2[2 * u + 1] = v.y;
    }
}

__device__ __forceinline__ float scan_step(u64 m2[16], const u64 W2[16],
                                           float ne, float a) {
    u64 en2 = pack2(ne, ne);
    u64 a2  = pack2(a, a);
    u64 acc0 = 0ull, acc1 = 0ull;
    #pragma unroll
    for (int p = 0; p < 16; p++) {
        u64 mo = m2[p];
        if (p & 1) acc1 = fma2(W2[p], mo, acc1);
        else       acc0 = fma2(W2[p], mo, acc0);
        u64 tmp = fma2(mo, en2, a2);          // a - e*m
        m2[p] = fma2(W2[p], tmp, mo);         // m + w*(a - e*m)
    }
    float x0, x1, y0, y1;
    unpack2(acc0, x0, x1);
    unpack2(acc1, y0, y1);
    return (x0 + x1) + (y0 + y1);
}

__global__ void __launch_bounds__(128, 1)
scan_kernel(const int* __restrict__ skills,
            const int* __restrict__ responses,
            const float* __restrict__ Mv0) {
    int tid  = threadIdx.x;
    int half = tid >> 6;                 // 0/1 -> batch within block
    int td   = tid & 63;
    int b    = blockIdx.x * 2 + half;
    int d0   = td;
    int d1   = td + 64;

    u64 m0[16], m1[16];
    #pragma unroll
    for (int p = 0; p < 16; p++) {
        m0[p] = pack2(__ldg(Mv0 + (2 * p) * DV + d0),
                      __ldg(Mv0 + (2 * p + 1) * DV + d0));
        m1[p] = pack2(__ldg(Mv0 + (2 * p) * DV + d1),
                      __ldg(Mv0 + (2 * p + 1) * DV + d1));
    }

    const int* srow = skills + b * T;
    const int* rrow = responses + b * T;
    float* rtp0 = g_rt + (b * TOUT) * DV + d0;
    float* rtp1 = g_rt + (b * TOUT) * DV + d1;

    int    sE[8];
    float2 E0[8], E1[8];
    #pragma unroll
    for (int k = 0; k < 8; k++) {
        int s = __ldg(srow + k);
        int q = s + NQ * __ldg(rrow + k);
        sE[k] = s;
        E0[k] = __ldg(g_ea + q * DV + d0);
        E1[k] = __ldg(g_ea + q * DV + d1);
    }
    int sCur = __ldg(srow + 8);
    int qCur = sCur + NQ * __ldg(rrow + 8);

    u64 WA[16], WB[16];
    scan_loadW(sE[0], WA);

#define SCAN_BODY_STEP(k, Wc, Wn)                                          \
    {                                                                      \
        scan_loadW(sE[((k) + 1) & 7], Wn);                                 \
        rtp0[(t + (k)) * DV] = scan_step(m0, Wc, E0[k].x, E0[k].y);        \
        rtp1[(t + (k)) * DV] = scan_step(m1, Wc, E1[k].x, E1[k].y);        \
        E0[k] = __ldg(g_ea + qCur * DV + d0);                              \
        E1[k] = __ldg(g_ea + qCur * DV + d1);                              \
        sE[k] = sCur;                                                      \
        int ni = t + 9 + (k); if (ni > T - 1) ni = T - 1;                  \
        sCur = __ldg(srow + ni);                                           \
        qCur = sCur + NQ * __ldg(rrow + ni);                               \
    }

    for (int t = 0; t < 248; t += 8) {
        SCAN_BODY_STEP(0, WA, WB)
        SCAN_BODY_STEP(1, WB, WA)
        SCAN_BODY_STEP(2, WA, WB)
        SCAN_BODY_STEP(3, WB, WA)
        SCAN_BODY_STEP(4, WA, WB)
        SCAN_BODY_STEP(5, WB, WA)
        SCAN_BODY_STEP(6, WA, WB)
        SCAN_BODY_STEP(7, WB, WA)
    }
#undef SCAN_BODY_STEP

    {
        const int t = 248;
#define SCAN_TAIL_STEP(k, Wc, Wn)                                          \
        {                                                                  \
            scan_loadW(sE[(k) + 1], Wn);                                   \
            rtp0[(t + (k)) * DV] = scan_step(m0, Wc, E0[k].x, E0[k].y);    \
            rtp1[(t + (k)) * DV] = scan_step(m1, Wc, E1[k].x, E1[k].y);    \
        }
        SCAN_TAIL_STEP(0, WA, WB)
        SCAN_TAIL_STEP(1, WB, WA)
        SCAN_TAIL_STEP(2, WA, WB)
        SCAN_TAIL_STEP(3, WB, WA)
        SCAN_TAIL_STEP(4, WA, WB)
        SCAN_TAIL_STEP(5, WB, WA)
        rtp0[254 * DV] = scan_step(m0, WA, E0[6].x, E0[6].y);
        rtp1[254 * DV] = scan_step(m1, WA, E1[6].x, E1[6].y);
#undef SCAN_TAIL_STEP
    }
}

// ---------------- readout via mma.sync (round-14, byte-exact) --------------
__global__ void __launch_bounds__(256)
readout_kernel(const float* __restrict__ p_W,
               const float* __restrict__ p_b,
               const int* __restrict__ skills,
               const int* __restrict__ responses,
               float* __restrict__ out,
               float* __restrict__ out2) {
    __shared__ __align__(16) float xs[64 * XPAD];
    __shared__ float red[64][2];

    int tid  = threadIdx.x;
    int lane = tid & 31;
    int wid  = tid >> 5;
    int wm   = wid & 3;
    int wn   = wid >> 2;
    int tg   = lane & 3;
    int gid  = lane >> 2;
    int row0 = blockIdx.x * 64;

    // stage X tile (64 x 128 fp32) with pad
    {
        const float4* src = reinterpret_cast<const float4*>(g_rt + row0 * DK);
        #pragma unroll
        for (int u = 0; u < 8; u++) {
            int fidx = tid + u * 256;          // 2048 float4
            int r = fidx >> 5, c4 = fidx & 31;
            *reinterpret_cast<float4*>(xs + r * XPAD + c4 * 4) = __ldg(src + fidx);
        }
    }
    __syncthreads();

    const float* xlo_row = xs + (wm * 16 + gid) * XPAD;
    const float* xhi_row = xlo_row + 8 * XPAD;

    float acc[8][4];
    #pragma unroll
    for (int nt = 0; nt < 8; nt++)
        #pragma unroll
        for (int e = 0; e < 4; e++) acc[nt][e] = 0.f;

    u32 AH[8][4];
    const u64* bbase = g_bf + (wn * 8) * 32 + lane;

    #pragma unroll
    for (int kt = 0; kt < 24; kt++) {
        u32 a[4];
        int kc = (kt & 7) * 16 + tg * 2;
        if (kt < 8) {
            float2 x0 = *reinterpret_cast<const float2*>(xlo_row + kc);
            float2 x1 = *reinterpret_cast<const float2*>(xhi_row + kc);
            float2 x2 = *reinterpret_cast<const float2*>(xlo_row + kc + 8);
            float2 x3 = *reinterpret_cast<const float2*>(xhi_row + kc + 8);
            a[0] = bfpack(x0.x, x0.y);
            a[1] = bfpack(x1.x, x1.y);
            a[2] = bfpack(x2.x, x2.y);
            a[3] = bfpack(x3.x, x3.y);
            #pragma unroll
            for (int r = 0; r < 4; r++) AH[kt][r] = a[r];
        } else if (kt < 16) {
            float2 xv[4];
            xv[0] = *reinterpret_cast<const float2*>(xlo_row + kc);
            xv[1] = *reinterpret_cast<const float2*>(xhi_row + kc);
            xv[2] = *reinterpret_cast<const float2*>(xlo_row + kc + 8);
            xv[3] = *reinterpret_cast<const float2*>(xhi_row + kc + 8);
            #pragma unroll
            for (int r = 0; r < 4; r++) {
                u32 h = AH[kt - 8][r];
                float h0 = __uint_as_float(h << 16);
                float h1 = __uint_as_float(h & 0xFFFF0000u);
                a[r] = bfpack(xv[r].x - h0, xv[r].y - h1);
            }
        } else {
            #pragma unroll
            for (int r = 0; r < 4; r++) a[r] = AH[kt - 16][r];
        }
        int bkt = (kt >= 16) ? (8 + (kt & 7)) : (kt & 7);
        const u64* bp = bbase + (bkt << 9);
        #pragma unroll
        for (int nt = 0; nt < 8; nt++) {
            u64 bv = __ldg(bp + nt * 32);
            mma16816(acc[nt], a, (u32)bv, (u32)(bv >> 32));
        }
    }

    // epilogue: + g gather, tanh, dot p_W, reduce
    int r_lo = row0 + wm * 16 + gid;
    int r_hi = r_lo + 8;
    int bb_lo = r_lo / TOUT, tt_lo = r_lo - bb_lo * TOUT;
    int bb_hi = r_hi / TOUT, tt_hi = r_hi - bb_hi * TOUT;
    int sk_lo = __ldg(skills + bb_lo * T + tt_lo);
    int sk_hi = __ldg(skills + bb_hi * T + tt_hi);

    float s_lo = 0.f, s_hi = 0.f;
    #pragma unroll
    for (int nt = 0; nt < 8; nt++) {
        int jg = wn * 64 + nt * 8 + tg * 2;
        float2 pw  = __ldg(reinterpret_cast<const float2*>(p_W + jg));
        float2 glo = __ldg(reinterpret_cast<const float2*>(g_g + sk_lo * DK + jg));
        float2 ghi = __ldg(reinterpret_cast<const float2*>(g_g + sk_hi * DK + jg));
        s_lo = fmaf(tanhf(acc[nt][0] + glo.x), pw.x, s_lo);
        s_lo = fmaf(tanhf(acc[nt][1] + glo.y), pw.y, s_lo);
        s_hi = fmaf(tanhf(acc[nt][2] + ghi.x), pw.x, s_hi);
        s_hi = fmaf(tanhf(acc[nt][3] + ghi.y), pw.y, s_hi);
    }
    s_lo += __shfl_xor_sync(0xffffffffu, s_lo, 1);
    s_lo += __shfl_xor_sync(0xffffffffu, s_lo, 2);
    s_hi += __shfl_xor_sync(0xffffffffu, s_hi, 1);
    s_hi += __shfl_xor_sync(0xffffffffu, s_hi, 2);
    if (tg == 0) {
        red[wm * 16 + gid][wn]     = s_lo;
        red[wm * 16 + gid + 8][wn] = s_hi;
    }
    __syncthreads();

    if (tid < 64) {
        float s = red[tid][0] + red[tid][1] + __ldg(p_b);
        int gr = row0 + tid;
        int bb = gr / TOUT;
        int tt = gr - bb * TOUT;
        out[gr]  = 1.0f / (1.0f + expf(-s));
        out2[gr] = (float)__ldg(responses + bb * T + tt + 1);
    }
}

// ---------------- launch ----------------------------------------------------
extern "C" void kernel_launch(void* const* d_in, const int* in_sizes, int n_in,
                              void* d_out, int out_size) {
    const int*   skills    = (const int*)  d_in[0];
    const int*   responses = (const int*)  d_in[1];
    const float* k_emb     = (const float*)d_in[2];
    const float* v_emb     = (const float*)d_in[3];
    const float* Mk        = (const float*)d_in[4];
    const float* Mv0       = (const float*)d_in[5];
    const float* f_W       = (const float*)d_in[6];
    const float* f_b       = (const float*)d_in[7];
    const float* p_W       = (const float*)d_in[8];
    const float* p_b       = (const float*)d_in[9];
    const float* e_W       = (const float*)d_in[10];
    const float* e_b       = (const float*)d_in[11];
    const float* a_W       = (const float*)d_in[12];
    const float* a_b       = (const float*)d_in[13];

    float* pred_out = (float*)d_out;
    float* true_out = pred_out + (out_size / 2);

    pre_pack_kernel<<<P1_BLOCKS, 256>>>(k_emb, Mk, f_W, f_b, e_W, a_W);

    pre_ea_mma_kernel<<<EA2_BLOCKS, 256>>>(v_emb, e_b, a_b);

    scan_kernel<<<B / 2, 128>>>(skills, responses, Mv0);

    readout_kernel<<<NROWS / 64, 256>>>(p_W, p_b, skills, responses,
                                        pred_out, true_out);
}